// round 5
// baseline (speedup 1.0000x reference)
#include <cuda_runtime.h>

typedef unsigned long long u64;

__device__ __forceinline__ u64 pk2(float a, float b) {
  u64 r; asm("mov.b64 %0, {%1, %2};" : "=l"(r) : "f"(a), "f"(b)); return r;
}
__device__ __forceinline__ void ffma2(u64& d, u64 a, u64 b) {
  asm("fma.rn.f32x2 %0, %1, %2, %0;" : "+l"(d) : "l"(a), "l"(b));
}
__device__ __forceinline__ float2 upk2(u64 v) {
  float2 r; asm("mov.b64 {%0, %1}, %2;" : "=f"(r.x), "=f"(r.y) : "l"(v)); return r;
}

// qkv scratch in windowed layout: [b(2)][wy(16)][wx(16)][ch(56)][Bs(8)][tok(64)]
#define NELEM_QKV (2*16*16*56*8*64)
__device__ float g_q[NELEM_QKV];
__device__ float g_k[NELEM_QKV];
__device__ float g_v[NELEM_QKV];

// ---------------------------------------------------------------------------
// All three grouped 3x3x3 convs, one launch (unchanged from R3).
// ---------------------------------------------------------------------------
__global__ __launch_bounds__(256) void conv_all_kernel(
    const float* __restrict__ x, const float* __restrict__ last,
    const float* __restrict__ Wq, const float* __restrict__ Wk,
    const float* __restrict__ Wv)
{
  const int z = blockIdx.z;
  int idx, sel;
  if (z < 112) { idx = z; sel = 0; }
  else { int zz = z - 112; idx = zz >> 1; sel = 1 + (zz & 1); }
  const float* in = (sel == 0) ? x : last;
  const float* W3 = (sel == 0) ? Wq : (sel == 1) ? Wk : Wv;
  float* outw     = (sel == 0) ? g_q : (sel == 1) ? g_k : g_v;

  const int b = idx / 56, o = idx % 56;
  const int h = blockIdx.y * 8 + threadIdx.y;
  const int w0 = threadIdx.x * 4;

  __shared__ float ws[54];
  const int tid = threadIdx.y * 32 + threadIdx.x;
  if (tid < 54) ws[tid] = W3[o * 54 + tid];
  __syncthreads();

  u64 acc2[8][2];
#pragma unroll
  for (int i = 0; i < 8; i++) { acc2[i][0] = 0ull; acc2[i][1] = 0ull; }

#pragma unroll
  for (int ci = 0; ci < 2; ci++) {
    const float* basec = in + (size_t)((b * 112 + o * 2 + ci) * 8) * 16384;
#pragma unroll
    for (int dh = 0; dh < 3; dh++) {
      const int hh = h + dh - 1;
      if (hh < 0 || hh > 127) continue;
      u64 w2p[3][3];
#pragma unroll
      for (int kd = 0; kd < 3; kd++)
#pragma unroll
        for (int dw = 0; dw < 3; dw++) {
          float wv = ws[ci * 27 + kd * 9 + dh * 3 + dw];
          w2p[kd][dw] = pk2(wv, wv);
        }
      const float* rowp = basec + hh * 128 + w0;
#pragma unroll
      for (int d = 0; d < 8; d++) {
        const float* p = rowp + d * 16384;
        float4 m4 = *(const float4*)p;
        float v[6];
        v[0] = (w0 > 0)   ? p[-1] : 0.f;
        v[1] = m4.x; v[2] = m4.y; v[3] = m4.z; v[4] = m4.w;
        v[5] = (w0 < 124) ? p[4]  : 0.f;
        u64 pv[5];
#pragma unroll
        for (int k = 0; k < 5; k++) pv[k] = pk2(v[k], v[k + 1]);
#pragma unroll
        for (int kd = 0; kd < 3; kd++) {
          const int Bs = d + 1 - kd;
          if (Bs < 0 || Bs > 7) continue;
#pragma unroll
          for (int dw = 0; dw < 3; dw++) {
            ffma2(acc2[Bs][0], w2p[kd][dw], pv[dw]);
            ffma2(acc2[Bs][1], w2p[kd][dw], pv[dw + 2]);
          }
        }
      }
    }
  }

  const int wy = h >> 3, ty = h & 7, wx = w0 >> 3, tx0 = w0 & 7;
  float* op = outw + (size_t)((((b * 16 + wy) * 16 + wx) * 56 + o) * 8) * 64
                   + ty * 8 + tx0;
#pragma unroll
  for (int Bs = 0; Bs < 8; Bs++) {
    float2 lo = upk2(acc2[Bs][0]), hi = upk2(acc2[Bs][1]);
    *(float4*)(op + Bs * 64) = make_float4(lo.x, lo.y, hi.x, hi.y);
  }
}

// ---------------------------------------------------------------------------
// Attention. Ownership (pair=tid>>3 -> rows 2p,2p+1; p8=tid&7 -> 8 j's).
// sim never touches smem: registers from QK^T through softmax to out-GEMM.
// ---------------------------------------------------------------------------
__device__ __forceinline__ float pick8(const float a[8], int i) {
  float r = a[0];
#pragma unroll
  for (int k = 1; k < 8; k++) r = (i == k) ? a[k] : r;
  return r;
}
__device__ __forceinline__ float sel8(float4 A, float4 B, int i) {
  float lo = (i & 2) ? ((i & 1) ? A.w : A.z) : ((i & 1) ? A.y : A.x);
  float hi = (i & 2) ? ((i & 1) ? B.w : B.z) : ((i & 1) ? B.y : B.x);
  return (i & 4) ? hi : lo;
}

__global__ __launch_bounds__(256, 3) void attn_kernel(
    const float* __restrict__ pcq_w, const float* __restrict__ pcq_b,
    const float* __restrict__ pck_w, const float* __restrict__ pck_b,
    const float* __restrict__ mlp1_w, const float* __restrict__ mlp2_w1,
    const float* __restrict__ mlp2_w2, const float* __restrict__ Wout,
    float* __restrict__ out)
{
  __shared__ __align__(16) float q_s[896], k_s[896], v_s[896];
  __shared__ __align__(16) float m1[64], w2[64], t1s[64], red[64];
  __shared__ float pcqw[14], pckw[14], woutc[28];
  __shared__ float theta_s, bq, bk;

  const int tid = threadIdx.x;
  const int bid = blockIdx.x;
  const int head = bid & 3, win = bid >> 2;
  const int b = win >> 8, wy = (win >> 4) & 15, wx = win & 15;

  if (tid < 64) { m1[tid] = mlp1_w[tid]; w2[tid] = mlp2_w2[tid]; }
  if (tid < 14) { pcqw[tid] = pcq_w[tid]; pckw[tid] = pck_w[tid]; }
  if (tid < 28) woutc[tid] = Wout[head * 28 + tid];
  if (tid == 0) { bq = pcq_b[0]; bk = pck_b[0]; }

  const size_t wbase = (size_t)((b * 16 + wy) * 16 + wx) * (56 * 8 * 64);
  const float4* gq = (const float4*)(g_q + wbase + head * 14 * 512);
  const float4* gk = (const float4*)(g_k + wbase + head * 14 * 512);
  const float4* gv = (const float4*)(g_v + wbase + head * 14 * 512);

  float4* q4 = (float4*)q_s; float4* k4 = (float4*)k_s; float4* v4 = (float4*)v_s;
  const float4* m14 = (const float4*)m1;

  const int pair = tid >> 3, p8 = tid & 7;
  const int r0 = 2 * pair;                      // rows r0, r0+1
  const int irow = tid >> 2, p4 = tid & 3;      // for theta MLP phase

  const int hh0 = wy * 8 + (r0 >> 3), ww0 = wx * 8 + (r0 & 7);

  for (int Bs = 0; Bs < 8; Bs++) {
    __syncthreads();
    // ---- A: load q,k,v slice to smem ----
    if (tid < 224) {
      int d = tid >> 4, t4 = tid & 15;
      int ga = d * 128 + Bs * 16 + t4;
      q4[d * 16 + t4] = gq[ga];
      k4[d * 16 + t4] = gk[ga];
      v4[d * 16 + t4] = gv[ga];
    }
    __syncthreads();

    // ---- C: sim rows in registers + sigma partials + t1 partial ----
    float a0[8], a1[8], sk[8];
    float sq0 = 0.f, sq1 = 0.f;
#pragma unroll
    for (int j = 0; j < 8; j++) { a0[j] = 0.f; a1[j] = 0.f; sk[j] = 0.f; }
#pragma unroll
    for (int d = 0; d < 14; d++) {
      float2 qq = *(const float2*)&q_s[d * 64 + r0];
      float4 kA = k4[d * 16 + p8 * 2];
      float4 kB = k4[d * 16 + p8 * 2 + 1];
      float pw = pcqw[d], kw = pckw[d];
      sq0 += qq.x * pw; sq1 += qq.y * pw;
      sk[0] += kA.x * kw; sk[1] += kA.y * kw; sk[2] += kA.z * kw; sk[3] += kA.w * kw;
      sk[4] += kB.x * kw; sk[5] += kB.y * kw; sk[6] += kB.z * kw; sk[7] += kB.w * kw;
      a0[0] += qq.x*kA.x; a0[1] += qq.x*kA.y; a0[2] += qq.x*kA.z; a0[3] += qq.x*kA.w;
      a0[4] += qq.x*kB.x; a0[5] += qq.x*kB.y; a0[6] += qq.x*kB.z; a0[7] += qq.x*kB.w;
      a1[0] += qq.y*kA.x; a1[1] += qq.y*kA.y; a1[2] += qq.y*kA.z; a1[3] += qq.y*kA.w;
      a1[4] += qq.y*kB.x; a1[5] += qq.y*kB.y; a1[6] += qq.y*kB.z; a1[7] += qq.y*kB.w;
    }
    // t1 partials (raw sim, minus diagonal)
    {
      float4 mA = m14[p8 * 2], mB = m14[p8 * 2 + 1];
      float tp0 = a0[0]*mA.x + a0[1]*mA.y + a0[2]*mA.z + a0[3]*mA.w
                + a0[4]*mB.x + a0[5]*mB.y + a0[6]*mB.z + a0[7]*mB.w;
      float tp1 = a1[0]*mA.x + a1[1]*mA.y + a1[2]*mA.z + a1[3]*mA.w
                + a1[4]*mB.x + a1[5]*mB.y + a1[6]*mB.z + a1[7]*mB.w;
      if ((r0 >> 3) == p8) {
        int l0 = r0 & 7, l1 = l0 + 1;
        tp0 -= pick8(a0, l0) * sel8(mA, mB, l0);
        tp1 -= pick8(a1, l1) * sel8(mA, mB, l1);
      }
#pragma unroll
      for (int off = 1; off < 8; off <<= 1) {
        tp0 += __shfl_xor_sync(0xffffffffu, tp0, off);
        tp1 += __shfl_xor_sync(0xffffffffu, tp1, off);
      }
      if (p8 == 0) *(float2*)&t1s[r0] = make_float2(tp0, tp1);
    }
    __syncthreads();

    // ---- E: t2 = leaky(t1 @ w1^T), theta = t2 . w2 ----
    {
      const float4* w1g = (const float4*)(mlp2_w1 + irow * 64 + p4 * 16);
      float s = 0.f;
#pragma unroll
      for (int c = 0; c < 4; c++) {
        int j0 = p4 * 16 + c * 4;
        float4 wv = __ldg(&w1g[c]);
        s += wv.x*t1s[j0] + wv.y*t1s[j0+1] + wv.z*t1s[j0+2] + wv.w*t1s[j0+3];
      }
      s += __shfl_xor_sync(0xffffffffu, s, 1);
      s += __shfl_xor_sync(0xffffffffu, s, 2);
      if (p4 == 0) {
        s = (s > 0.f) ? s : 0.1f * s;
        red[irow] = s * w2[irow];
      }
    }
    __syncthreads();
    if (tid < 32) {
      float s = red[tid] + red[tid + 32];
#pragma unroll
      for (int off = 16; off > 0; off >>= 1)
        s += __shfl_xor_sync(0xffffffffu, s, off);
      if (tid == 0) theta_s = s;
    }
    __syncthreads();

    // ---- FG: scale+softmax+mask in registers, out-GEMM, butterfly, store ----
    {
      const float th = theta_s;
      const float Sq0 = sq0 + bq, Sq1 = sq1 + bq;
      float m0 = -1e30f, m1r = -1e30f;
#pragma unroll
      for (int j = 0; j < 8; j++) {
        float skj = sk[j] + bk;
        a0[j] = a0[j] * Sq0 * skj;
        a1[j] = a1[j] * Sq1 * skj;
        m0 = fmaxf(m0, a0[j]); m1r = fmaxf(m1r, a1[j]);
      }
#pragma unroll
      for (int off = 1; off < 8; off <<= 1) {
        m0  = fmaxf(m0,  __shfl_xor_sync(0xffffffffu, m0,  off));
        m1r = fmaxf(m1r, __shfl_xor_sync(0xffffffffu, m1r, off));
      }
      float s0 = 0.f, s1 = 0.f;
#pragma unroll
      for (int j = 0; j < 8; j++) {
        float x0 = a0[j], x1 = a1[j];
        float e0 = __expf(x0 - m0), e1 = __expf(x1 - m1r);
        s0 += e0; s1 += e1;
        a0[j] = (x0 > th) ? e0 : 0.f;
        a1[j] = (x1 > th) ? e1 : 0.f;
      }
#pragma unroll
      for (int off = 1; off < 8; off <<= 1) {
        s0 += __shfl_xor_sync(0xffffffffu, s0, off);
        s1 += __shfl_xor_sync(0xffffffffu, s1, off);
      }
      const float i0 = 1.f / s0, i1 = 1.f / s1;
#pragma unroll
      for (int j = 0; j < 8; j++) { a0[j] *= i0; a1[j] *= i1; }

      // out partials over my 8 j's, all 14 d
      float o0[14], o1[14];
#pragma unroll
      for (int d = 0; d < 14; d++) {
        float4 vA = v4[d * 16 + p8 * 2];
        float4 vB = v4[d * 16 + p8 * 2 + 1];
        o0[d] = a0[0]*vA.x + a0[1]*vA.y + a0[2]*vA.z + a0[3]*vA.w
              + a0[4]*vB.x + a0[5]*vB.y + a0[6]*vB.z + a0[7]*vB.w;
        o1[d] = a1[0]*vA.x + a1[1]*vA.y + a1[2]*vA.z + a1[3]*vA.w
              + a1[4]*vB.x + a1[5]*vB.y + a1[6]*vB.z + a1[7]*vB.w;
      }

      // split-butterfly over the 8 p8 lanes: lane ends with d=p8 and d=p8+8
#pragma unroll
      for (int s = 0; s < 14; s++) {
        o0[s] += __shfl_xor_sync(0xffffffffu, o0[s], 4);
        o1[s] += __shfl_xor_sync(0xffffffffu, o1[s], 4);
      }
      const bool b2 = (p8 & 4) != 0;
      float c0[8], c1[8];
      c0[0]=b2?o0[4]:o0[0];   c1[0]=b2?o1[4]:o1[0];
      c0[1]=b2?o0[5]:o0[1];   c1[1]=b2?o1[5]:o1[1];
      c0[2]=b2?o0[6]:o0[2];   c1[2]=b2?o1[6]:o1[2];
      c0[3]=b2?o0[7]:o0[3];   c1[3]=b2?o1[7]:o1[3];
      c0[4]=b2?o0[12]:o0[8];  c1[4]=b2?o1[12]:o1[8];
      c0[5]=b2?o0[13]:o0[9];  c1[5]=b2?o1[13]:o1[9];
      c0[6]=b2?0.f:o0[10];    c1[6]=b2?0.f:o1[10];
      c0[7]=b2?0.f:o0[11];    c1[7]=b2?0.f:o1[11];
#pragma unroll
      for (int mI = 0; mI < 8; mI++) {
        c0[mI] += __shfl_xor_sync(0xffffffffu, c0[mI], 2);
        c1[mI] += __shfl_xor_sync(0xffffffffu, c1[mI], 2);
      }
      const bool b1 = (p8 & 2) != 0;
      float e0[4], e1[4];
      e0[0]=b1?c0[2]:c0[0];  e1[0]=b1?c1[2]:c1[0];
      e0[1]=b1?c0[3]:c0[1];  e1[1]=b1?c1[3]:c1[1];
      e0[2]=b1?c0[6]:c0[4];  e1[2]=b1?c1[6]:c1[4];
      e0[3]=b1?c0[7]:c0[5];  e1[3]=b1?c1[7]:c1[5];
#pragma unroll
      for (int nI = 0; nI < 4; nI++) {
        e0[nI] += __shfl_xor_sync(0xffffffffu, e0[nI], 1);
        e1[nI] += __shfl_xor_sync(0xffffffffu, e1[nI], 1);
      }
      const bool b0 = (p8 & 1) != 0;
      const float f00 = b0 ? e0[1] : e0[0];   // row r0, d = p8
      const float f10 = b0 ? e1[1] : e1[0];   // row r1, d = p8
      const float f01 = b0 ? e0[3] : e0[2];   // row r0, d = p8+8
      const float f11 = b0 ? e1[3] : e1[2];   // row r1, d = p8+8

      const size_t sp0 = (size_t)Bs * 16384 + hh0 * 128 + ww0;
      const size_t cbase = (size_t)(b * 112 + head * 28) * 131072 + sp0;
      {
        const int d0c = p8;
        float wA = woutc[d0c * 2], wB = woutc[d0c * 2 + 1];
        size_t a0p = cbase + (size_t)(2 * d0c) * 131072;
        *(float2*)&out[a0p]          = make_float2(f00 * wA, f10 * wA);
        *(float2*)&out[a0p + 131072] = make_float2(f00 * wB, f10 * wB);
      }
      if (p8 < 6) {
        const int d1c = p8 + 8;
        float wA = woutc[d1c * 2], wB = woutc[d1c * 2 + 1];
        size_t a1p = cbase + (size_t)(2 * d1c) * 131072;
        *(float2*)&out[a1p]          = make_float2(f01 * wA, f11 * wA);
        *(float2*)&out[a1p + 131072] = make_float2(f01 * wB, f11 * wB);
      }
    }
  }
}

extern "C" void kernel_launch(void* const* d_in, const int* in_sizes, int n_in,
                              void* d_out, int out_size) {
  (void)in_sizes; (void)n_in; (void)out_size;
  const float* x      = (const float*)d_in[0];
  const float* last   = (const float*)d_in[1];
  const float* Wq     = (const float*)d_in[2];
  const float* Wk     = (const float*)d_in[3];
  const float* Wv     = (const float*)d_in[4];
  const float* Wout   = (const float*)d_in[5];
  const float* pcq_w  = (const float*)d_in[6];
  const float* pcq_b  = (const float*)d_in[7];
  const float* pck_w  = (const float*)d_in[8];
  const float* pck_b  = (const float*)d_in[9];
  const float* mlp1_w = (const float*)d_in[10];
  const float* mlp2w1 = (const float*)d_in[11];
  const float* mlp2w2 = (const float*)d_in[12];
  float* out = (float*)d_out;

  conv_all_kernel<<<dim3(1, 16, 336), dim3(32, 8)>>>(x, last, Wq, Wk, Wv);
  attn_kernel<<<2048, 256>>>(pcq_w, pcq_b, pck_w, pck_b,
                             mlp1_w, mlp2w1, mlp2w2, Wout, out);
}

// round 6
// speedup vs baseline: 1.2122x; 1.2122x over previous
#include <cuda_runtime.h>

typedef unsigned long long u64;

__device__ __forceinline__ u64 pk2(float a, float b) {
  u64 r; asm("mov.b64 %0, {%1, %2};" : "=l"(r) : "f"(a), "f"(b)); return r;
}
__device__ __forceinline__ void ffma2(u64& d, u64 a, u64 b) {
  asm("fma.rn.f32x2 %0, %1, %2, %0;" : "+l"(d) : "l"(a), "l"(b));
}
__device__ __forceinline__ float2 upk2(u64 v) {
  float2 r; asm("mov.b64 {%0, %1}, %2;" : "=f"(r.x), "=f"(r.y) : "l"(v)); return r;
}

// qkv scratch in windowed layout: [b(2)][wy(16)][wx(16)][ch(56)][Bs(8)][tok(64)]
#define NELEM_QKV (2*16*16*56*8*64)
__device__ float g_q[NELEM_QKV];
__device__ float g_k[NELEM_QKV];
__device__ float g_v[NELEM_QKV];

// ---------------------------------------------------------------------------
// All three grouped 3x3x3 convs, one launch. Halo values come from warp
// shuffles (the warp covers the full 128-wide row), not scalar LDGs.
// ---------------------------------------------------------------------------
__global__ __launch_bounds__(256) void conv_all_kernel(
    const float* __restrict__ x, const float* __restrict__ last,
    const float* __restrict__ Wq, const float* __restrict__ Wk,
    const float* __restrict__ Wv)
{
  const int z = blockIdx.z;
  int idx, sel;
  if (z < 112) { idx = z; sel = 0; }
  else { int zz = z - 112; idx = zz >> 1; sel = 1 + (zz & 1); }
  const float* in = (sel == 0) ? x : last;
  const float* W3 = (sel == 0) ? Wq : (sel == 1) ? Wk : Wv;
  float* outw     = (sel == 0) ? g_q : (sel == 1) ? g_k : g_v;

  const int b = idx / 56, o = idx % 56;
  const int h = blockIdx.y * 8 + threadIdx.y;
  const int tx = threadIdx.x;
  const int w0 = tx * 4;

  __shared__ float ws[54];
  const int tid = threadIdx.y * 32 + tx;
  if (tid < 54) ws[tid] = W3[o * 54 + tid];
  __syncthreads();

  u64 acc2[8][2];
#pragma unroll
  for (int i = 0; i < 8; i++) { acc2[i][0] = 0ull; acc2[i][1] = 0ull; }

#pragma unroll
  for (int ci = 0; ci < 2; ci++) {
    const float* basec = in + (size_t)((b * 112 + o * 2 + ci) * 8) * 16384;
#pragma unroll
    for (int dh = 0; dh < 3; dh++) {
      const int hh = h + dh - 1;
      if (hh < 0 || hh > 127) continue;
      u64 w2p[3][3];
#pragma unroll
      for (int kd = 0; kd < 3; kd++)
#pragma unroll
        for (int dw = 0; dw < 3; dw++) {
          float wv = ws[ci * 27 + kd * 9 + dh * 3 + dw];
          w2p[kd][dw] = pk2(wv, wv);
        }
      const float* rowp = basec + hh * 128 + w0;
#pragma unroll
      for (int d = 0; d < 8; d++) {
        const float* p = rowp + d * 16384;
        float4 m4 = *(const float4*)p;
        // halo via warp shuffle: warp spans the full 128-wide image row
        float vl = __shfl_up_sync(0xffffffffu, m4.w, 1);
        float vr = __shfl_down_sync(0xffffffffu, m4.x, 1);
        float v[6];
        v[0] = (tx == 0)  ? 0.f : vl;
        v[1] = m4.x; v[2] = m4.y; v[3] = m4.z; v[4] = m4.w;
        v[5] = (tx == 31) ? 0.f : vr;
        u64 pv[5];
#pragma unroll
        for (int k = 0; k < 5; k++) pv[k] = pk2(v[k], v[k + 1]);
#pragma unroll
        for (int kd = 0; kd < 3; kd++) {
          const int Bs = d + 1 - kd;
          if (Bs < 0 || Bs > 7) continue;
#pragma unroll
          for (int dw = 0; dw < 3; dw++) {
            ffma2(acc2[Bs][0], w2p[kd][dw], pv[dw]);
            ffma2(acc2[Bs][1], w2p[kd][dw], pv[dw + 2]);
          }
        }
      }
    }
  }

  const int wy = h >> 3, ty = h & 7, wx = w0 >> 3, tx0 = w0 & 7;
  float* op = outw + (size_t)((((b * 16 + wy) * 16 + wx) * 56 + o) * 8) * 64
                   + ty * 8 + tx0;
#pragma unroll
  for (int Bs = 0; Bs < 8; Bs++) {
    float2 lo = upk2(acc2[Bs][0]), hi = upk2(acc2[Bs][1]);
    *(float4*)(op + Bs * 64) = make_float4(lo.x, lo.y, hi.x, hi.y);
  }
}

// ---------------------------------------------------------------------------
// Attention (R3 structure — best measured). E phase now reads t1s as float4.
// ---------------------------------------------------------------------------
#define SPAD 68   // sim row stride in floats

__global__ __launch_bounds__(256) void attn_kernel(
    const float* __restrict__ pcq_w, const float* __restrict__ pcq_b,
    const float* __restrict__ pck_w, const float* __restrict__ pck_b,
    const float* __restrict__ mlp1_w, const float* __restrict__ mlp2_w1,
    const float* __restrict__ mlp2_w2, const float* __restrict__ Wout,
    float* __restrict__ out)
{
  __shared__ __align__(16) float q_s[896], k_s[896], v_s[896];
  __shared__ __align__(16) float sim[64 * SPAD];
  __shared__ __align__(16) float m1[64], w2[64], t1s[64];
  __shared__ __align__(16) float Sqs[64], Sks[64], red[64];
  __shared__ float pcqw[14], pckw[14], woutc[28];
  __shared__ float theta_s, bq, bk;

  const int tid = threadIdx.x;
  const int bid = blockIdx.x;
  const int head = bid & 3, win = bid >> 2;
  const int b = win >> 8, wy = (win >> 4) & 15, wx = win & 15;

  if (tid < 64) { m1[tid] = mlp1_w[tid]; w2[tid] = mlp2_w2[tid]; }
  if (tid < 14) { pcqw[tid] = pcq_w[tid]; pckw[tid] = pck_w[tid]; }
  if (tid < 28) woutc[tid] = Wout[head * 28 + tid];
  if (tid == 0) { bq = pcq_b[0]; bk = pck_b[0]; }

  const size_t wbase = (size_t)((b * 16 + wy) * 16 + wx) * (56 * 8 * 64);
  const float4* gq = (const float4*)(g_q + wbase + head * 14 * 512);
  const float4* gk = (const float4*)(g_k + wbase + head * 14 * 512);
  const float4* gv = (const float4*)(g_v + wbase + head * 14 * 512);

  float4* q4 = (float4*)q_s; float4* k4 = (float4*)k_s; float4* v4 = (float4*)v_s;
  float4* sim4 = (float4*)sim;
  const float4* Sks4 = (const float4*)Sks;
  const float4* m14  = (const float4*)m1;
  const float4* t14  = (const float4*)t1s;

  const int irow = tid >> 2, p4 = tid & 3;     // quad ownership
  const int it = tid >> 4, jt = tid & 15;      // 4x4 tile ownership

  const int hh = wy * 8 + (irow >> 3), ww = wx * 8 + (irow & 7);

  for (int Bs = 0; Bs < 8; Bs++) {
    __syncthreads();   // protect smem reuse across slices
    // ---- A: load q,k,v slice; v quarter-permuted ----
    if (tid < 224) {
      int d = tid >> 4, t4 = tid & 15;
      int ga = d * 128 + Bs * 16 + t4;
      q4[d * 16 + t4] = gq[ga];
      k4[d * 16 + t4] = gk[ga];
      v4[d * 16 + (t4 & 3) * 4 + (t4 >> 2)] = gv[ga];
    }
    __syncthreads();

    // ---- B: sigma projections (Sks stored pre-permuted) ----
    if (tid < 128) {
      int i = tid & 63;
      if (tid < 64) {
        float s = bq;
#pragma unroll
        for (int d = 0; d < 14; d++) s += q_s[d * 64 + i] * pcqw[d];
        Sqs[i] = s;
      } else {
        float s = bk;
#pragma unroll
        for (int d = 0; d < 14; d++) s += k_s[d * 64 + i] * pckw[d];
        Sks[(((i >> 2) & 3) * 4 + (i >> 4)) * 4 + (i & 3)] = s;
      }
    }

    // ---- C: sim = q^T k (4x4 tiles) + fold t1 partials via shfl ----
    {
      float a00=0,a01=0,a02=0,a03=0, a10=0,a11=0,a12=0,a13=0;
      float a20=0,a21=0,a22=0,a23=0, a30=0,a31=0,a32=0,a33=0;
#pragma unroll
      for (int d = 0; d < 14; d++) {
        float4 qv = q4[d * 16 + it];
        float4 kv = k4[d * 16 + jt];
        a00 += qv.x*kv.x; a01 += qv.x*kv.y; a02 += qv.x*kv.z; a03 += qv.x*kv.w;
        a10 += qv.y*kv.x; a11 += qv.y*kv.y; a12 += qv.y*kv.z; a13 += qv.y*kv.w;
        a20 += qv.z*kv.x; a21 += qv.z*kv.y; a22 += qv.z*kv.z; a23 += qv.z*kv.w;
        a30 += qv.w*kv.x; a31 += qv.w*kv.y; a32 += qv.w*kv.z; a33 += qv.w*kv.w;
      }
      const int rbase = it * 4;
      sim4[(rbase+0) * (SPAD/4) + jt] = make_float4(a00,a01,a02,a03);
      sim4[(rbase+1) * (SPAD/4) + jt] = make_float4(a10,a11,a12,a13);
      sim4[(rbase+2) * (SPAD/4) + jt] = make_float4(a20,a21,a22,a23);
      sim4[(rbase+3) * (SPAD/4) + jt] = make_float4(a30,a31,a32,a33);

      float4 mv = m14[jt];
      float pr0 = a00*mv.x + a01*mv.y + a02*mv.z + a03*mv.w;
      float pr1 = a10*mv.x + a11*mv.y + a12*mv.z + a13*mv.w;
      float pr2 = a20*mv.x + a21*mv.y + a22*mv.z + a23*mv.w;
      float pr3 = a30*mv.x + a31*mv.y + a32*mv.z + a33*mv.w;
      if (it == jt) {
        pr0 -= a00 * mv.x; pr1 -= a11 * mv.y;
        pr2 -= a22 * mv.z; pr3 -= a33 * mv.w;
      }
#pragma unroll
      for (int off = 1; off < 16; off <<= 1) {
        pr0 += __shfl_xor_sync(0xffffffffu, pr0, off);
        pr1 += __shfl_xor_sync(0xffffffffu, pr1, off);
        pr2 += __shfl_xor_sync(0xffffffffu, pr2, off);
        pr3 += __shfl_xor_sync(0xffffffffu, pr3, off);
      }
      if (jt == 0) {
        t1s[rbase + 0] = pr0; t1s[rbase + 1] = pr1;
        t1s[rbase + 2] = pr2; t1s[rbase + 3] = pr3;
      }
    }
    __syncthreads();

    // ---- E: t2 = leaky(t1 @ w1^T), theta = t2 . w2 (t1s as float4) ----
    {
      const float4* w1g = (const float4*)(mlp2_w1 + irow * 64 + p4 * 16);
      float s = 0.f;
#pragma unroll
      for (int c = 0; c < 4; c++) {
        float4 wv = __ldg(&w1g[c]);
        float4 tv = t14[p4 * 4 + c];
        s += wv.x * tv.x + wv.y * tv.y + wv.z * tv.z + wv.w * tv.w;
      }
      s += __shfl_xor_sync(0xffffffffu, s, 1);
      s += __shfl_xor_sync(0xffffffffu, s, 2);
      if (p4 == 0) {
        s = (s > 0.f) ? s : 0.1f * s;
        red[irow] = s * w2[irow];
      }
    }
    __syncthreads();
    if (tid < 32) {
      float s = red[tid] + red[tid + 32];
#pragma unroll
      for (int off = 16; off > 0; off >>= 1)
        s += __shfl_xor_sync(0xffffffffu, s, off);
      if (tid == 0) theta_s = s;
    }
    __syncthreads();

    // ---- FG fused: scale, softmax, mask, out-GEMM, store ----
    {
      const float sq = Sqs[irow];
      const float th = theta_s;
      float a[16];
      float m = -1e30f;
#pragma unroll
      for (int c = 0; c < 4; c++) {
        float4 sv = sim4[irow * (SPAD/4) + p4 * 4 + c];
        float4 kv = Sks4[c * 4 + p4];          // permuted: holds Sk[p4*16+c*4..]
        a[c*4+0] = sv.x * sq * kv.x; a[c*4+1] = sv.y * sq * kv.y;
        a[c*4+2] = sv.z * sq * kv.z; a[c*4+3] = sv.w * sq * kv.w;
        m = fmaxf(m, fmaxf(fmaxf(a[c*4+0], a[c*4+1]), fmaxf(a[c*4+2], a[c*4+3])));
      }
      m = fmaxf(m, __shfl_xor_sync(0xffffffffu, m, 1));
      m = fmaxf(m, __shfl_xor_sync(0xffffffffu, m, 2));
      float sum = 0.f;
#pragma unroll
      for (int e = 0; e < 16; e++) {
        float xv = a[e];
        float ev = __expf(xv - m);
        sum += ev;
        a[e] = (xv > th) ? ev : 0.f;
      }
      sum += __shfl_xor_sync(0xffffffffu, sum, 1);
      sum += __shfl_xor_sync(0xffffffffu, sum, 2);
      const float r = 1.f / sum;
#pragma unroll
      for (int e = 0; e < 16; e++) a[e] *= r;

      const size_t sp = (size_t)Bs * 16384 + hh * 128 + ww;
      const size_t cb = (size_t)(b * 112 + head * 28) * 131072 + sp;
#pragma unroll
      for (int half = 0; half < 2; half++) {
        float oacc[7] = {0.f,0.f,0.f,0.f,0.f,0.f,0.f};
#pragma unroll
        for (int dd = 0; dd < 7; dd++) {
          const int d = half * 7 + dd;
#pragma unroll
          for (int c = 0; c < 4; c++) {
            float4 vv = v4[d * 16 + c * 4 + p4];   // permuted: v[d][p4*16+c*4..]
            oacc[dd] += a[c*4+0]*vv.x + a[c*4+1]*vv.y
                      + a[c*4+2]*vv.z + a[c*4+3]*vv.w;
          }
        }
#pragma unroll
        for (int dd = 0; dd < 7; dd++) {
          float s = oacc[dd];
          s += __shfl_xor_sync(0xffffffffu, s, 1);
          s += __shfl_xor_sync(0xffffffffu, s, 2);
          oacc[dd] = s;
        }
#pragma unroll
        for (int k = 0; k < 2; k++) {
          const int dd = p4 + 4 * k;
          if (dd < 7) {
            const int d = half * 7 + dd;
            out[cb + (size_t)(2 * d)     * 131072] = oacc[dd] * woutc[d * 2 + 0];
            out[cb + (size_t)(2 * d + 1) * 131072] = oacc[dd] * woutc[d * 2 + 1];
          }
        }
      }
    }
  }
}

extern "C" void kernel_launch(void* const* d_in, const int* in_sizes, int n_in,
                              void* d_out, int out_size) {
  (void)in_sizes; (void)n_in; (void)out_size;
  const float* x      = (const float*)d_in[0];
  const float* last   = (const float*)d_in[1];
  const float* Wq     = (const float*)d_in[2];
  const float* Wk     = (const float*)d_in[3];
  const float* Wv     = (const float*)d_in[4];
  const float* Wout   = (const float*)d_in[5];
  const float* pcq_w  = (const float*)d_in[6];
  const float* pcq_b  = (const float*)d_in[7];
  const float* pck_w  = (const float*)d_in[8];
  const float* pck_b  = (const float*)d_in[9];
  const float* mlp1_w = (const float*)d_in[10];
  const float* mlp2w1 = (const float*)d_in[11];
  const float* mlp2w2 = (const float*)d_in[12];
  float* out = (float*)d_out;

  conv_all_kernel<<<dim3(1, 16, 336), dim3(32, 8)>>>(x, last, Wq, Wk, Wv);
  attn_kernel<<<2048, 256>>>(pcq_w, pcq_b, pck_w, pck_b,
                             mlp1_w, mlp2w1, mlp2w2, Wout, out);
}

// round 7
// speedup vs baseline: 1.2283x; 1.0133x over previous
#include <cuda_runtime.h>

// qkv scratch in windowed layout: [b(2)][wy(16)][wx(16)][ch(56)][Bs(8)][tok(64)]
#define NELEM_QKV (2*16*16*56*8*64)
__device__ float g_q[NELEM_QKV];
__device__ float g_k[NELEM_QKV];
__device__ float g_v[NELEM_QKV];

// ---------------------------------------------------------------------------
// All three grouped 3x3x3 convs, one launch. Halo via warp shuffle.
// Plain compiler FFMA (A/B against the f32x2 asm path).
// ---------------------------------------------------------------------------
__global__ __launch_bounds__(256) void conv_all_kernel(
    const float* __restrict__ x, const float* __restrict__ last,
    const float* __restrict__ Wq, const float* __restrict__ Wk,
    const float* __restrict__ Wv)
{
  const int z = blockIdx.z;
  int idx, sel;
  if (z < 112) { idx = z; sel = 0; }
  else { int zz = z - 112; idx = zz >> 1; sel = 1 + (zz & 1); }
  const float* in = (sel == 0) ? x : last;
  const float* W3 = (sel == 0) ? Wq : (sel == 1) ? Wk : Wv;
  float* outw     = (sel == 0) ? g_q : (sel == 1) ? g_k : g_v;

  const int b = idx / 56, o = idx % 56;
  const int h = blockIdx.y * 8 + threadIdx.y;
  const int tx = threadIdx.x;
  const int w0 = tx * 4;

  __shared__ float ws[54];
  const int tid = threadIdx.y * 32 + tx;
  if (tid < 54) ws[tid] = W3[o * 54 + tid];
  __syncthreads();

  float acc[8][4];
#pragma unroll
  for (int i = 0; i < 8; i++) {
    acc[i][0] = 0.f; acc[i][1] = 0.f; acc[i][2] = 0.f; acc[i][3] = 0.f;
  }

#pragma unroll
  for (int ci = 0; ci < 2; ci++) {
    const float* basec = in + (size_t)((b * 112 + o * 2 + ci) * 8) * 16384;
#pragma unroll
    for (int dh = 0; dh < 3; dh++) {
      const int hh = h + dh - 1;
      if (hh < 0 || hh > 127) continue;
      float w9[3][3];
#pragma unroll
      for (int kd = 0; kd < 3; kd++)
#pragma unroll
        for (int dw = 0; dw < 3; dw++)
          w9[kd][dw] = ws[ci * 27 + kd * 9 + dh * 3 + dw];
      const float* rowp = basec + hh * 128 + w0;
#pragma unroll
      for (int d = 0; d < 8; d++) {
        const float* p = rowp + d * 16384;
        float4 m4 = *(const float4*)p;
        // halo via warp shuffle: warp spans the full 128-wide image row
        float vl = __shfl_up_sync(0xffffffffu, m4.w, 1);
        float vr = __shfl_down_sync(0xffffffffu, m4.x, 1);
        float v[6];
        v[0] = (tx == 0)  ? 0.f : vl;
        v[1] = m4.x; v[2] = m4.y; v[3] = m4.z; v[4] = m4.w;
        v[5] = (tx == 31) ? 0.f : vr;
#pragma unroll
        for (int kd = 0; kd < 3; kd++) {
          const int Bs = d + 1 - kd;
          if (Bs < 0 || Bs > 7) continue;
#pragma unroll
          for (int dw = 0; dw < 3; dw++) {
            const float wv = w9[kd][dw];
            acc[Bs][0] += wv * v[dw + 0];
            acc[Bs][1] += wv * v[dw + 1];
            acc[Bs][2] += wv * v[dw + 2];
            acc[Bs][3] += wv * v[dw + 3];
          }
        }
      }
    }
  }

  const int wy = h >> 3, ty = h & 7, wx = w0 >> 3, tx0 = w0 & 7;
  float* op = outw + (size_t)((((b * 16 + wy) * 16 + wx) * 56 + o) * 8) * 64
                   + ty * 8 + tx0;
#pragma unroll
  for (int Bs = 0; Bs < 8; Bs++) {
    *(float4*)(op + Bs * 64) =
        make_float4(acc[Bs][0], acc[Bs][1], acc[Bs][2], acc[Bs][3]);
  }
}

// ---------------------------------------------------------------------------
// Attention. t1 computed via identity t1_i = q_i.Kbar - m1_i*(q_i.k_i),
// Kbar = sum_j m1_j k_j (folded into phase A from registers).
// C is a pure 4x4-tiled GEMM; sigma/t1 ride on warps 4-7 in the C region.
// ---------------------------------------------------------------------------
#define SPAD 68   // sim row stride in floats

__global__ __launch_bounds__(256) void attn_kernel(
    const float* __restrict__ pcq_w, const float* __restrict__ pcq_b,
    const float* __restrict__ pck_w, const float* __restrict__ pck_b,
    const float* __restrict__ mlp1_w, const float* __restrict__ mlp2_w1,
    const float* __restrict__ mlp2_w2, const float* __restrict__ Wout,
    float* __restrict__ out)
{
  __shared__ __align__(16) float q_s[896], k_s[896], v_s[896];
  __shared__ __align__(16) float sim[64 * SPAD];
  __shared__ __align__(16) float m1[64], w2[64], t1s[64];
  __shared__ __align__(16) float Sqs[64], Sks[64], red[64];
  __shared__ __align__(16) float kbar[16];
  __shared__ float pcqw[14], pckw[14], woutc[28];
  __shared__ float theta_s, bq, bk;

  const int tid = threadIdx.x;
  const int bid = blockIdx.x;
  const int head = bid & 3, win = bid >> 2;
  const int b = win >> 8, wy = (win >> 4) & 15, wx = win & 15;

  if (tid < 64) { m1[tid] = mlp1_w[tid]; w2[tid] = mlp2_w2[tid]; }
  if (tid < 14) { pcqw[tid] = pcq_w[tid]; pckw[tid] = pck_w[tid]; }
  if (tid < 28) woutc[tid] = Wout[head * 28 + tid];
  if (tid == 0) { bq = pcq_b[0]; bk = pck_b[0]; }

  const size_t wbase = (size_t)((b * 16 + wy) * 16 + wx) * (56 * 8 * 64);
  const float4* gq = (const float4*)(g_q + wbase + head * 14 * 512);
  const float4* gk = (const float4*)(g_k + wbase + head * 14 * 512);
  const float4* gv = (const float4*)(g_v + wbase + head * 14 * 512);

  float4* q4 = (float4*)q_s; float4* k4 = (float4*)k_s; float4* v4 = (float4*)v_s;
  float4* sim4 = (float4*)sim;
  const float4* Sks4 = (const float4*)Sks;
  const float4* m14  = (const float4*)m1;
  const float4* t14  = (const float4*)t1s;

  const int irow = tid >> 2, p4 = tid & 3;     // quad ownership
  const int it = tid >> 4, jt = tid & 15;      // 4x4 tile ownership

  const int hh = wy * 8 + (irow >> 3), ww = wx * 8 + (irow & 7);

  for (int Bs = 0; Bs < 8; Bs++) {
    __syncthreads();   // protect smem reuse across slices
    // ---- A: load q,k,v slice (v quarter-permuted) + Kbar from registers ----
    if (tid < 224) {   // warps 0..6, fully uniform
      int d = tid >> 4, t4 = tid & 15;
      int ga = d * 128 + Bs * 16 + t4;
      float4 kk = gk[ga];
      q4[d * 16 + t4] = gq[ga];
      k4[d * 16 + t4] = kk;
      v4[d * 16 + (t4 & 3) * 4 + (t4 >> 2)] = gv[ga];
      float4 mm = m14[t4];
      float pr = kk.x*mm.x + kk.y*mm.y + kk.z*mm.z + kk.w*mm.w;
      pr += __shfl_xor_sync(0xffffffffu, pr, 1);
      pr += __shfl_xor_sync(0xffffffffu, pr, 2);
      pr += __shfl_xor_sync(0xffffffffu, pr, 4);
      pr += __shfl_xor_sync(0xffffffffu, pr, 8);
      if (t4 == 0) kbar[d] = pr;
    }
    __syncthreads();

    // ---- C: sim = q^T k (pure 4x4 register-tiled GEMM) ----
    {
      float a00=0,a01=0,a02=0,a03=0, a10=0,a11=0,a12=0,a13=0;
      float a20=0,a21=0,a22=0,a23=0, a30=0,a31=0,a32=0,a33=0;
#pragma unroll
      for (int d = 0; d < 14; d++) {
        float4 qv = q4[d * 16 + it];
        float4 kv = k4[d * 16 + jt];
        a00 += qv.x*kv.x; a01 += qv.x*kv.y; a02 += qv.x*kv.z; a03 += qv.x*kv.w;
        a10 += qv.y*kv.x; a11 += qv.y*kv.y; a12 += qv.y*kv.z; a13 += qv.y*kv.w;
        a20 += qv.z*kv.x; a21 += qv.z*kv.y; a22 += qv.z*kv.z; a23 += qv.z*kv.w;
        a30 += qv.w*kv.x; a31 += qv.w*kv.y; a32 += qv.w*kv.z; a33 += qv.w*kv.w;
      }
      const int rbase = it * 4;
      sim4[(rbase+0) * (SPAD/4) + jt] = make_float4(a00,a01,a02,a03);
      sim4[(rbase+1) * (SPAD/4) + jt] = make_float4(a10,a11,a12,a13);
      sim4[(rbase+2) * (SPAD/4) + jt] = make_float4(a20,a21,a22,a23);
      sim4[(rbase+3) * (SPAD/4) + jt] = make_float4(a30,a31,a32,a33);
    }
    // ---- sigma/t1 extras on warps 4-7 (same region, one barrier) ----
    if (tid >= 128 && tid < 192) {            // warps 4,5: Sk (pre-permuted)
      int j = tid - 128;
      float s = bk;
#pragma unroll
      for (int d = 0; d < 14; d++) s += k_s[d * 64 + j] * pckw[d];
      Sks[(((j >> 2) & 3) * 4 + (j >> 4)) * 4 + (j & 3)] = s;
    } else if (tid >= 192) {                  // warps 6,7: Sq, diag, t1
      int i = tid - 192;
      float sq = bq, qkb = 0.f, dg = 0.f;
#pragma unroll
      for (int d = 0; d < 14; d++) {
        float qv = q_s[d * 64 + i];
        float kv = k_s[d * 64 + i];
        sq  += qv * pcqw[d];
        qkb += qv * kbar[d];
        dg  += qv * kv;
      }
      Sqs[i] = sq;
      t1s[i] = qkb - m1[i] * dg;
    }
    __syncthreads();

    // ---- E: t2 = leaky(t1 @ w1^T), theta = t2 . w2 ----
    {
      const float4* w1g = (const float4*)(mlp2_w1 + irow * 64 + p4 * 16);
      float s = 0.f;
#pragma unroll
      for (int c = 0; c < 4; c++) {
        float4 wv = __ldg(&w1g[c]);
        float4 tv = t14[p4 * 4 + c];
        s += wv.x * tv.x + wv.y * tv.y + wv.z * tv.z + wv.w * tv.w;
      }
      s += __shfl_xor_sync(0xffffffffu, s, 1);
      s += __shfl_xor_sync(0xffffffffu, s, 2);
      if (p4 == 0) {
        s = (s > 0.f) ? s : 0.1f * s;
        red[irow] = s * w2[irow];
      }
    }
    __syncthreads();
    if (tid < 32) {
      float s = red[tid] + red[tid + 32];
#pragma unroll
      for (int off = 16; off > 0; off >>= 1)
        s += __shfl_xor_sync(0xffffffffu, s, off);
      if (tid == 0) theta_s = s;
    }
    __syncthreads();

    // ---- FG fused: scale, softmax, mask, out-GEMM, store ----
    {
      const float sq = Sqs[irow];
      const float th = theta_s;
      float a[16];
      float m = -1e30f;
#pragma unroll
      for (int c = 0; c < 4; c++) {
        float4 sv = sim4[irow * (SPAD/4) + p4 * 4 + c];
        float4 kv = Sks4[c * 4 + p4];          // permuted: holds Sk[p4*16+c*4..]
        a[c*4+0] = sv.x * sq * kv.x; a[c*4+1] = sv.y * sq * kv.y;
        a[c*4+2] = sv.z * sq * kv.z; a[c*4+3] = sv.w * sq * kv.w;
        m = fmaxf(m, fmaxf(fmaxf(a[c*4+0], a[c*4+1]), fmaxf(a[c*4+2], a[c*4+3])));
      }
      m = fmaxf(m, __shfl_xor_sync(0xffffffffu, m, 1));
      m = fmaxf(m, __shfl_xor_sync(0xffffffffu, m, 2));
      float sum = 0.f;
#pragma unroll
      for (int e = 0; e < 16; e++) {
        float xv = a[e];
        float ev = __expf(xv - m);
        sum += ev;
        a[e] = (xv > th) ? ev : 0.f;
      }
      sum += __shfl_xor_sync(0xffffffffu, sum, 1);
      sum += __shfl_xor_sync(0xffffffffu, sum, 2);
      const float r = 1.f / sum;
#pragma unroll
      for (int e = 0; e < 16; e++) a[e] *= r;

      const size_t sp = (size_t)Bs * 16384 + hh * 128 + ww;
      const size_t cb = (size_t)(b * 112 + head * 28) * 131072 + sp;
#pragma unroll
      for (int half = 0; half < 2; half++) {
        float oacc[7] = {0.f,0.f,0.f,0.f,0.f,0.f,0.f};
#pragma unroll
        for (int dd = 0; dd < 7; dd++) {
          const int d = half * 7 + dd;
#pragma unroll
          for (int c = 0; c < 4; c++) {
            float4 vv = v4[d * 16 + c * 4 + p4];   // permuted: v[d][p4*16+c*4..]
            oacc[dd] += a[c*4+0]*vv.x + a[c*4+1]*vv.y
                      + a[c*4+2]*vv.z + a[c*4+3]*vv.w;
          }
        }
#pragma unroll
        for (int dd = 0; dd < 7; dd++) {
          float s = oacc[dd];
          s += __shfl_xor_sync(0xffffffffu, s, 1);
          s += __shfl_xor_sync(0xffffffffu, s, 2);
          oacc[dd] = s;
        }
#pragma unroll
        for (int k = 0; k < 2; k++) {
          const int dd = p4 + 4 * k;
          if (dd < 7) {
            const int d = half * 7 + dd;
            out[cb + (size_t)(2 * d)     * 131072] = oacc[dd] * woutc[d * 2 + 0];
            out[cb + (size_t)(2 * d + 1) * 131072] = oacc[dd] * woutc[d * 2 + 1];
          }
        }
      }
    }
  }
}

extern "C" void kernel_launch(void* const* d_in, const int* in_sizes, int n_in,
                              void* d_out, int out_size) {
  (void)in_sizes; (void)n_in; (void)out_size;
  const float* x      = (const float*)d_in[0];
  const float* last   = (const float*)d_in[1];
  const float* Wq     = (const float*)d_in[2];
  const float* Wk     = (const float*)d_in[3];
  const float* Wv     = (const float*)d_in[4];
  const float* Wout   = (const float*)d_in[5];
  const float* pcq_w  = (const float*)d_in[6];
  const float* pcq_b  = (const float*)d_in[7];
  const float* pck_w  = (const float*)d_in[8];
  const float* pck_b  = (const float*)d_in[9];
  const float* mlp1_w = (const float*)d_in[10];
  const float* mlp2w1 = (const float*)d_in[11];
  const float* mlp2w2 = (const float*)d_in[12];
  float* out = (float*)d_out;

  conv_all_kernel<<<dim3(1, 16, 336), dim3(32, 8)>>>(x, last, Wq, Wk, Wv);
  attn_kernel<<<2048, 256>>>(pcq_w, pcq_b, pck_w, pck_b,
                             mlp1_w, mlp2w1, mlp2w2, Wout, out);
}